// round 6
// baseline (speedup 1.0000x reference)
#include <cuda_runtime.h>

#define ALPHA 0.9f
#define BETA  0.8f
#define TH    1.0f

// ---------------- scratch (device globals; no allocation) ----------------
__device__ float g_a1[128 * 32 * 55 * 55];   // conv1 out
__device__ float g_a2[128 * 64 * 26 * 26];   // conv2 out
__device__ float g_a3[128 * 64 * 24 * 24];   // conv3 out (== flattened x[:, :36864])
__device__ float g_part[37 * 128 * 128];     // fc1 split-K partials [kb][b][j]
__device__ float g_spk1[10 * 128 * 128];     // spk1 trajectory [t][b][j]
__device__ float g_h2[10 * 128 * 256];       // h2 [t][b][j2]
__device__ float g_spk2[10 * 128 * 256];     // spk2 trajectory

// =====================================================================
// conv1: (128,3,224,224) -> (128,32,55,55), 8x8 stride 4, ReLU
// grid (55, 128) = (oy, n); 128 threads; active 112 = 28 ox-pairs x 4 oc-groups
// =====================================================================
__global__ __launch_bounds__(128) void conv1_k(const float* __restrict__ state,
                                               const float* __restrict__ cw1,
                                               const float* __restrict__ cb1) {
    __shared__ float s_in[3 * 8 * 228];   // row stride 228 (pad: masked ox=55 reads stay in-bounds)
    __shared__ float s_w[32 * 193];       // oc stride 193 (bank spread)
    const int oy = blockIdx.x, n = blockIdx.y, tid = threadIdx.x;

    for (int idx = tid; idx < 5376; idx += 128) {
        int row = idx / 224, ix = idx % 224;       // row = ic*8 + ky
        int ic = row >> 3, ky = row & 7;
        s_in[row * 228 + ix] = state[((n * 3 + ic) * 224 + oy * 4 + ky) * 224 + ix];
    }
    for (int idx = tid; idx < 6144; idx += 128) {
        int oc = idx / 192, rem = idx % 192;
        s_w[oc * 193 + rem] = cw1[idx];
    }
    __syncthreads();

    if (tid < 112) {
        const int p = tid % 28, ocg = tid / 28;
        const int ox0 = 2 * p, ox1 = 2 * p + 1;
        float acc[2][8];
#pragma unroll
        for (int i = 0; i < 2; i++)
#pragma unroll
            for (int j = 0; j < 8; j++) acc[i][j] = 0.f;

        for (int ic = 0; ic < 3; ic++)
#pragma unroll
            for (int ky = 0; ky < 8; ky++) {
                const float* ip = &s_in[(ic * 8 + ky) * 228];
                const float* wp = &s_w[(ocg * 8) * 193 + ic * 64 + ky * 8];
#pragma unroll
                for (int kx = 0; kx < 8; kx++) {
                    float x0 = ip[ox0 * 4 + kx];
                    float x1 = ip[ox1 * 4 + kx];   // p=27 reads pad (result discarded)
#pragma unroll
                    for (int j = 0; j < 8; j++) {
                        float w = wp[j * 193 + kx];
                        acc[0][j] += x0 * w;
                        acc[1][j] += x1 * w;
                    }
                }
            }
#pragma unroll
        for (int j = 0; j < 8; j++) {
            int oc = ocg * 8 + j;
            float b = cb1[oc];
            float* op = &g_a1[((n * 32 + oc) * 55 + oy) * 55];
            op[ox0] = fmaxf(acc[0][j] + b, 0.f);
            if (ox1 < 55) op[ox1] = fmaxf(acc[1][j] + b, 0.f);
        }
    }
}

// =====================================================================
// conv2: (128,32,55,55) -> (128,64,26,26), 4x4 stride 2, ReLU
// grid (26, 128); 128 threads; active 104 = 13 ox-pairs x 8 oc-groups
// ic chunked by 8 (4 chunks)
// =====================================================================
__global__ __launch_bounds__(128) void conv2_k(const float* __restrict__ cw2,
                                               const float* __restrict__ cb2) {
    __shared__ float s_in[8 * 4 * 55];    // 1760
    __shared__ float s_w[64 * 129];       // 8256
    const int oy = blockIdx.x, n = blockIdx.y, tid = threadIdx.x;
    const int p = tid % 13, ocg = tid / 13;
    float acc[2][8];
#pragma unroll
    for (int i = 0; i < 2; i++)
#pragma unroll
        for (int j = 0; j < 8; j++) acc[i][j] = 0.f;

    for (int c = 0; c < 4; c++) {
        __syncthreads();
        for (int idx = tid; idx < 1760; idx += 128) {
            int icl = idx / 220, rem = idx % 220;
            int ky = rem / 55, ix = rem % 55;
            s_in[idx] = g_a1[((n * 32 + c * 8 + icl) * 55 + oy * 2 + ky) * 55 + ix];
        }
        for (int idx = tid; idx < 8192; idx += 128) {
            int oc = idx >> 7, rem = idx & 127;    // rem = icl*16 + ky*4 + kx
            s_w[oc * 129 + rem] = cw2[oc * 512 + c * 128 + rem];
        }
        __syncthreads();
        if (tid < 104) {
            for (int icl = 0; icl < 8; icl++)
#pragma unroll
                for (int ky = 0; ky < 4; ky++) {
                    const float* ip = &s_in[(icl * 4 + ky) * 55];
                    const float* wp = &s_w[(ocg * 8) * 129 + icl * 16 + ky * 4];
#pragma unroll
                    for (int kx = 0; kx < 4; kx++) {
                        float x0 = ip[p * 4 + kx];       // ox0 = 2p
                        float x1 = ip[p * 4 + 2 + kx];   // ox1 = 2p+1
#pragma unroll
                        for (int j = 0; j < 8; j++) {
                            float w = wp[j * 129 + kx];
                            acc[0][j] += x0 * w;
                            acc[1][j] += x1 * w;
                        }
                    }
                }
        }
    }
    if (tid < 104) {
        const int ox0 = 2 * p, ox1 = 2 * p + 1;
#pragma unroll
        for (int j = 0; j < 8; j++) {
            int oc = ocg * 8 + j;
            float b = cb2[oc];
            float* op = &g_a2[((n * 64 + oc) * 26 + oy) * 26];
            op[ox0] = fmaxf(acc[0][j] + b, 0.f);
            op[ox1] = fmaxf(acc[1][j] + b, 0.f);
        }
    }
}

// =====================================================================
// conv3: (128,64,26,26) -> (128,64,24,24), 3x3 stride 1, ReLU
// grid (24, 128); 128 threads; active 96 = 12 ox-pairs x 8 oc-groups
// ic chunked by 16 (4 chunks)
// =====================================================================
__global__ __launch_bounds__(128) void conv3_k(const float* __restrict__ cw3,
                                               const float* __restrict__ cb3) {
    __shared__ float s_in[16 * 3 * 26];   // 1248
    __shared__ float s_w[64 * 145];       // 9280
    const int oy = blockIdx.x, n = blockIdx.y, tid = threadIdx.x;
    const int p = tid % 12, ocg = tid / 12;
    float acc[2][8];
#pragma unroll
    for (int i = 0; i < 2; i++)
#pragma unroll
        for (int j = 0; j < 8; j++) acc[i][j] = 0.f;

    for (int c = 0; c < 4; c++) {
        __syncthreads();
        for (int idx = tid; idx < 1248; idx += 128) {
            int icl = idx / 78, rem = idx % 78;
            int ky = rem / 26, ix = rem % 26;
            s_in[idx] = g_a2[((n * 64 + c * 16 + icl) * 26 + oy + ky) * 26 + ix];
        }
        for (int idx = tid; idx < 9216; idx += 128) {
            int oc = idx / 144, rem = idx % 144;   // rem = icl*9 + ky*3 + kx
            s_w[oc * 145 + rem] = cw3[oc * 576 + c * 144 + rem];
        }
        __syncthreads();
        if (tid < 96) {
            for (int icl = 0; icl < 16; icl++)
#pragma unroll
                for (int ky = 0; ky < 3; ky++) {
                    const float* ip = &s_in[(icl * 3 + ky) * 26];
                    const float* wp = &s_w[(ocg * 8) * 145 + icl * 9 + ky * 3];
#pragma unroll
                    for (int kx = 0; kx < 3; kx++) {
                        float x0 = ip[2 * p + kx];
                        float x1 = ip[2 * p + 1 + kx];
#pragma unroll
                        for (int j = 0; j < 8; j++) {
                            float w = wp[j * 145 + kx];
                            acc[0][j] += x0 * w;
                            acc[1][j] += x1 * w;
                        }
                    }
                }
        }
    }
    if (tid < 96) {
        const int ox0 = 2 * p, ox1 = 2 * p + 1;
#pragma unroll
        for (int j = 0; j < 8; j++) {
            int oc = ocg * 8 + j;
            float b = cb3[oc];
            float* op = &g_a3[((n * 64 + oc) * 24 + oy) * 24];
            op[ox0] = fmaxf(acc[0][j] + b, 0.f);
            op[ox1] = fmaxf(acc[1][j] + b, 0.f);
        }
    }
}

// =====================================================================
// fc1 split-K: partial[kb][b][j] = sum_{k in chunk kb} x[b][k] * w1[j][k]
// kb 0..35: 1024 cols from g_a3; kb 36: 90 cols of history.
// grid (2, 2, 37): 64x64 output tile, 256 threads, 4x4 per thread.
// =====================================================================
__global__ __launch_bounds__(256) void fc1_k(const float* __restrict__ hist,
                                             const float* __restrict__ w1) {
    __shared__ float Xs[64][33];
    __shared__ float Ws[64][33];
    const int kb = blockIdx.z, b0 = blockIdx.x * 64, j0 = blockIdx.y * 64;
    const int tid = threadIdx.x;
    const int klen = (kb == 36) ? 90 : 1024;
    const int kbase = kb * 1024;                 // for kb==36 this is 36864
    const int mi0 = (tid & 15) * 4, ji0 = (tid >> 4) * 4;
    float acc[4][4];
#pragma unroll
    for (int i = 0; i < 4; i++)
#pragma unroll
        for (int j = 0; j < 4; j++) acc[i][j] = 0.f;

    for (int ks = 0; ks < klen; ks += 32) {
        __syncthreads();
#pragma unroll
        for (int i = 0; i < 8; i++) {
            int e = tid + i * 256;
            int r = e >> 5, kk = e & 31;
            int k = ks + kk;
            float xv = 0.f, wv = 0.f;
            if (k < klen) {
                int gk = kbase + k;
                xv = (kb == 36) ? hist[(b0 + r) * 90 + k]
                                : g_a3[(b0 + r) * 36864 + gk];
                wv = w1[(j0 + r) * 36954 + gk];
            }
            Xs[r][kk] = xv;
            Ws[r][kk] = wv;
        }
        __syncthreads();
#pragma unroll
        for (int kk = 0; kk < 32; kk++) {
            float xv[4], wv[4];
#pragma unroll
            for (int i = 0; i < 4; i++) xv[i] = Xs[mi0 + i][kk];
#pragma unroll
            for (int j = 0; j < 4; j++) wv[j] = Ws[ji0 + j][kk];
#pragma unroll
            for (int i = 0; i < 4; i++)
#pragma unroll
                for (int j = 0; j < 4; j++) acc[i][j] += xv[i] * wv[j];
        }
    }
#pragma unroll
    for (int i = 0; i < 4; i++)
#pragma unroll
        for (int j = 0; j < 4; j++)
            g_part[(kb * 128 + b0 + mi0 + i) * 128 + j0 + ji0 + j] = acc[i][j];
}

// =====================================================================
// lif1: reduce partials -> h1 (+b1); run stage-1 LIF trajectory per (b,j).
// h1 is constant across t so the whole trajectory is elementwise-local.
// =====================================================================
__global__ __launch_bounds__(256) void lif1_k(const float* __restrict__ b1) {
    int gid = blockIdx.x * 256 + threadIdx.x;   // < 16384
    int b = gid >> 7, j = gid & 127;
    float h = b1[j];
#pragma unroll 1
    for (int kb = 0; kb < 37; kb++) h += g_part[(kb * 128 + b) * 128 + j];
    float mem = 0.f, syn = 0.f;
#pragma unroll
    for (int t = 0; t < 10; t++) {
        syn = ALPHA * syn + h;
        mem = BETA * mem + syn;
        float s = (mem > TH) ? 1.f : 0.f;
        mem -= s * TH;
        g_spk1[t * 16384 + gid] = s;
    }
}

// =====================================================================
// gemm2: h2[m][j2] = spk1[m] @ w2.T + b2, m = t*128+b (M=1280, N=256, K=128)
// grid (20, 4): 64x64 tiles, 256 threads, 4x4 per thread.
// =====================================================================
__global__ __launch_bounds__(256) void gemm2_k(const float* __restrict__ w2,
                                               const float* __restrict__ b2) {
    __shared__ float Xs[64][33];
    __shared__ float Ws[64][33];
    const int m0 = blockIdx.x * 64, j0 = blockIdx.y * 64, tid = threadIdx.x;
    const int mi0 = (tid & 15) * 4, ji0 = (tid >> 4) * 4;
    float acc[4][4];
#pragma unroll
    for (int i = 0; i < 4; i++)
#pragma unroll
        for (int j = 0; j < 4; j++) acc[i][j] = 0.f;

    for (int ks = 0; ks < 128; ks += 32) {
        __syncthreads();
#pragma unroll
        for (int i = 0; i < 8; i++) {
            int e = tid + i * 256, r = e >> 5, kk = e & 31;
            Xs[r][kk] = g_spk1[(m0 + r) * 128 + ks + kk];
            Ws[r][kk] = w2[(j0 + r) * 128 + ks + kk];
        }
        __syncthreads();
#pragma unroll
        for (int kk = 0; kk < 32; kk++) {
            float xv[4], wv[4];
#pragma unroll
            for (int i = 0; i < 4; i++) xv[i] = Xs[mi0 + i][kk];
#pragma unroll
            for (int j = 0; j < 4; j++) wv[j] = Ws[ji0 + j][kk];
#pragma unroll
            for (int i = 0; i < 4; i++)
#pragma unroll
                for (int j = 0; j < 4; j++) acc[i][j] += xv[i] * wv[j];
        }
    }
#pragma unroll
    for (int i = 0; i < 4; i++)
#pragma unroll
        for (int j = 0; j < 4; j++)
            g_h2[(m0 + mi0 + i) * 256 + j0 + ji0 + j] = acc[i][j] + b2[j0 + ji0 + j];
}

// =====================================================================
// lif2: stage-2 LIF trajectory per (b,j2) over its h2[t] sequence.
// =====================================================================
__global__ __launch_bounds__(256) void lif2_k() {
    int b = blockIdx.x, j = threadIdx.x;
    float mem = 0.f, syn = 0.f;
#pragma unroll
    for (int t = 0; t < 10; t++) {
        float h = g_h2[(t * 128 + b) * 256 + j];
        syn = ALPHA * syn + h;
        mem = BETA * mem + syn;
        float s = (mem > TH) ? 1.f : 0.f;
        mem -= s * TH;
        g_spk2[(t * 128 + b) * 256 + j] = s;
    }
}

// =====================================================================
// out: per batch row b: h3[t][o] = spk2[t][b] . w3[o] + b3[o] (90 dots of K=256),
// then stage-3 accumulation over t; out[b][o] = pot/10.
// grid 128, 96 threads.
// =====================================================================
__global__ __launch_bounds__(96) void out_k(const float* __restrict__ w3,
                                            const float* __restrict__ b3,
                                            float* __restrict__ out) {
    __shared__ float s_s[10 * 256];
    __shared__ float s_w[9 * 256];
    __shared__ float s_h[90];
    const int b = blockIdx.x, tid = threadIdx.x;

    for (int idx = tid; idx < 2560; idx += 96) {
        int t = idx >> 8, k = idx & 255;
        s_s[idx] = g_spk2[(t * 128 + b) * 256 + k];
    }
    for (int idx = tid; idx < 2304; idx += 96) s_w[idx] = w3[idx];
    __syncthreads();

    if (tid < 90) {
        int t = tid / 9, o = tid % 9;
        float a = b3[o];
        for (int k = 0; k < 256; k++) a += s_s[t * 256 + k] * s_w[o * 256 + k];
        s_h[tid] = a;
    }
    __syncthreads();

    if (tid < 9) {
        float syn = 0.f, mem = 0.f, pot = 0.f;
#pragma unroll
        for (int t = 0; t < 10; t++) {
            syn = ALPHA * syn + s_h[t * 9 + tid];
            mem = BETA * mem + syn;
            pot += mem;
        }
        out[b * 9 + tid] = pot / 10.0f;
    }
}

// =====================================================================
extern "C" void kernel_launch(void* const* d_in, const int* in_sizes, int n_in,
                              void* d_out, int out_size) {
    const float* state = (const float*)d_in[0];
    const float* hist  = (const float*)d_in[1];
    const float* cw1 = (const float*)d_in[2];
    const float* cb1 = (const float*)d_in[3];
    const float* cw2 = (const float*)d_in[4];
    const float* cb2 = (const float*)d_in[5];
    const float* cw3 = (const float*)d_in[6];
    const float* cb3 = (const float*)d_in[7];
    const float* w1  = (const float*)d_in[8];
    const float* b1  = (const float*)d_in[9];
    const float* w2  = (const float*)d_in[10];
    const float* b2  = (const float*)d_in[11];
    const float* w3  = (const float*)d_in[12];
    const float* b3  = (const float*)d_in[13];
    float* out = (float*)d_out;

    conv1_k<<<dim3(55, 128), 128>>>(state, cw1, cb1);
    conv2_k<<<dim3(26, 128), 128>>>(cw2, cb2);
    conv3_k<<<dim3(24, 128), 128>>>(cw3, cb3);
    fc1_k<<<dim3(2, 2, 37), 256>>>(hist, w1);
    lif1_k<<<64, 256>>>(b1);
    gemm2_k<<<dim3(20, 4), 256>>>(w2, b2);
    lif2_k<<<128, 256>>>();
    out_k<<<128, 96>>>(w3, b3, out);
}

// round 9
// speedup vs baseline: 1.2467x; 1.2467x over previous
#include <cuda_runtime.h>

#define ALPHA 0.9f
#define BETA  0.8f
#define TH    1.0f

typedef unsigned long long ull;

__device__ __forceinline__ ull fma2(ull a, ull b, ull c) {
    ull d;
    asm("fma.rn.f32x2 %0, %1, %2, %3;" : "=l"(d) : "l"(a), "l"(b), "l"(c));
    return d;
}
__device__ __forceinline__ ull pk2(float v) {
    ull r;
    asm("mov.b64 %0, {%1, %2};" : "=l"(r) : "f"(v), "f"(v));
    return r;
}
__device__ __forceinline__ void unpk(ull a, float& lo, float& hi) {
    asm("mov.b64 {%0, %1}, %2;" : "=f"(lo), "=f"(hi) : "l"(a));
}

// ---------------- scratch (device globals; no allocation) ----------------
__device__ float g_a1[128 * 32 * 55 * 55];
__device__ float g_a2[128 * 64 * 26 * 26];
__device__ float g_a3[128 * 64 * 24 * 24];
__device__ float g_part[145 * 128 * 128];
__device__ float g_spk1[10 * 128 * 128];
__device__ float g_h2[10 * 128 * 256];
__device__ float g_spk2[10 * 128 * 256];

// =====================================================================
// conv1: (128,3,224,224) -> (128,32,55,55), 8x8 s4, ReLU. grid (55,128), 128 thr
// thread (p<28: ox pair (2p,2p+1), ocg<4: 8 oc as 4 f32x2 pairs)
// smem: 21888 + 24576 = 46464 B
// =====================================================================
__global__ __launch_bounds__(128) void conv1_k(const float* __restrict__ state,
                                               const float* __restrict__ cw1,
                                               const float* __restrict__ cb1) {
    __shared__ __align__(16) float s_in[3 * 8 * 228];
    __shared__ __align__(16) float s_w[192 * 32];     // [rem][oc], stride 32
    const int oy = blockIdx.x, n = blockIdx.y, tid = threadIdx.x;

    for (int idx = tid; idx < 5376; idx += 128) {
        int row = idx / 224, ix = idx % 224;
        int ic = row >> 3, ky = row & 7;
        s_in[row * 228 + ix] = state[((n * 3 + ic) * 224 + oy * 4 + ky) * 224 + ix];
    }
    for (int idx = tid; idx < 6144; idx += 128) {
        int oc = idx / 192, rem = idx % 192;
        s_w[rem * 32 + oc] = cw1[idx];
    }
    __syncthreads();

    if (tid < 112) {
        const int p = tid % 28, ocg = tid / 28;
        ull acc[2][4];
#pragma unroll
        for (int i = 0; i < 2; i++)
#pragma unroll
            for (int j = 0; j < 4; j++) acc[i][j] = 0ull;

        for (int ic = 0; ic < 3; ic++)
#pragma unroll
            for (int ky = 0; ky < 8; ky++) {
                // ox0=2p needs x in [8p, 8p+7]; ox1 needs [8p+4, 8p+11]
                const float* ip = &s_in[(ic * 8 + ky) * 228 + 8 * p];
                float4 wa = *(const float4*)ip;
                float4 wb = *(const float4*)(ip + 4);
                float4 wc = *(const float4*)(ip + 8);
                float win[12] = {wa.x, wa.y, wa.z, wa.w, wb.x, wb.y, wb.z, wb.w,
                                 wc.x, wc.y, wc.z, wc.w};
                const int base = (ic * 64 + ky * 8) * 32 + ocg * 8;
#pragma unroll
                for (int kx = 0; kx < 8; kx++) {
                    ull x0 = pk2(win[kx]);
                    ull x1 = pk2(win[kx + 4]);
                    const ulonglong2* wp = (const ulonglong2*)&s_w[base + kx * 32];
                    ulonglong2 W0 = wp[0], W1 = wp[1];
                    acc[0][0] = fma2(x0, W0.x, acc[0][0]);
                    acc[0][1] = fma2(x0, W0.y, acc[0][1]);
                    acc[0][2] = fma2(x0, W1.x, acc[0][2]);
                    acc[0][3] = fma2(x0, W1.y, acc[0][3]);
                    acc[1][0] = fma2(x1, W0.x, acc[1][0]);
                    acc[1][1] = fma2(x1, W0.y, acc[1][1]);
                    acc[1][2] = fma2(x1, W1.x, acc[1][2]);
                    acc[1][3] = fma2(x1, W1.y, acc[1][3]);
                }
            }
        const int ox0 = 2 * p, ox1 = 2 * p + 1;
#pragma unroll
        for (int j = 0; j < 4; j++) {
            int oc = ocg * 8 + 2 * j;
            float b0v = cb1[oc], b1v = cb1[oc + 1];
            float l0, h0, l1, h1;
            unpk(acc[0][j], l0, h0);
            unpk(acc[1][j], l1, h1);
            float* op0 = &g_a1[((n * 32 + oc) * 55 + oy) * 55];
            float* op1 = op0 + 55 * 55;
            op0[ox0] = fmaxf(l0 + b0v, 0.f);
            op1[ox0] = fmaxf(h0 + b1v, 0.f);
            if (ox1 < 55) {
                op0[ox1] = fmaxf(l1 + b0v, 0.f);
                op1[ox1] = fmaxf(h1 + b1v, 0.f);
            }
        }
    }
}

// =====================================================================
// conv2: (128,32,55,55) -> (128,64,26,26), 4x4 s2, ReLU. grid (13,128), 224 thr
// block covers oy pair; thread (ox<26, ocg<8) -> 2 oy x 8 oc
// s_in row stride 56 (even -> float2-aligned)
// =====================================================================
__global__ __launch_bounds__(224) void conv2_k(const float* __restrict__ cw2,
                                               const float* __restrict__ cb2) {
    __shared__ __align__(16) float s_in[8 * 6 * 56];    // 2688
    __shared__ __align__(16) float s_w[128 * 68];       // [rem][oc], stride 68
    const int oyp = blockIdx.x, n = blockIdx.y, tid = threadIdx.x;
    const int ox = tid % 26, ocg = tid / 26;
    ull acc[2][4];
#pragma unroll
    for (int i = 0; i < 2; i++)
#pragma unroll
        for (int j = 0; j < 4; j++) acc[i][j] = 0ull;

    for (int c = 0; c < 4; c++) {
        __syncthreads();
        for (int idx = tid; idx < 2640; idx += 224) {
            int icl = idx / 330, rem = idx % 330;
            int r = rem / 55, ix = rem % 55;
            s_in[(icl * 6 + r) * 56 + ix] =
                g_a1[((n * 32 + c * 8 + icl) * 55 + 4 * oyp + r) * 55 + ix];
        }
        for (int idx = tid; idx < 8192; idx += 224) {
            int oc = idx >> 7, rem = idx & 127;
            s_w[rem * 68 + oc] = cw2[oc * 512 + c * 128 + rem];
        }
        __syncthreads();
        if (tid < 208) {
            for (int icl = 0; icl < 8; icl++)
#pragma unroll
                for (int ky = 0; ky < 4; ky++) {
                    const float* r0 = &s_in[(icl * 6 + ky) * 56 + 2 * ox];
                    const float* r1 = r0 + 2 * 56;
                    float2 xa = *(const float2*)r0, xb = *(const float2*)(r0 + 2);
                    float2 ya = *(const float2*)r1, yb = *(const float2*)(r1 + 2);
                    float xw[4] = {xa.x, xa.y, xb.x, xb.y};
                    float yw[4] = {ya.x, ya.y, yb.x, yb.y};
                    const int base = (icl * 16 + ky * 4) * 68 + ocg * 8;
#pragma unroll
                    for (int kx = 0; kx < 4; kx++) {
                        ull xp = pk2(xw[kx]);
                        ull yp = pk2(yw[kx]);
                        const ulonglong2* wp = (const ulonglong2*)&s_w[base + kx * 68];
                        ulonglong2 W0 = wp[0], W1 = wp[1];
                        acc[0][0] = fma2(xp, W0.x, acc[0][0]);
                        acc[0][1] = fma2(xp, W0.y, acc[0][1]);
                        acc[0][2] = fma2(xp, W1.x, acc[0][2]);
                        acc[0][3] = fma2(xp, W1.y, acc[0][3]);
                        acc[1][0] = fma2(yp, W0.x, acc[1][0]);
                        acc[1][1] = fma2(yp, W0.y, acc[1][1]);
                        acc[1][2] = fma2(yp, W1.x, acc[1][2]);
                        acc[1][3] = fma2(yp, W1.y, acc[1][3]);
                    }
                }
        }
    }
    if (tid < 208) {
#pragma unroll
        for (int loy = 0; loy < 2; loy++) {
            int oyg = oyp * 2 + loy;
#pragma unroll
            for (int j = 0; j < 4; j++) {
                int oc = ocg * 8 + 2 * j;
                float lo, hi;
                unpk(acc[loy][j], lo, hi);
                g_a2[((n * 64 + oc) * 26 + oyg) * 26 + ox] = fmaxf(lo + cb2[oc], 0.f);
                g_a2[((n * 64 + oc + 1) * 26 + oyg) * 26 + ox] = fmaxf(hi + cb2[oc + 1], 0.f);
            }
        }
    }
}

// =====================================================================
// conv3: (128,64,26,26) -> (128,64,24,24), 3x3 s1, ReLU. grid (12,128), 192 thr
// thread (ox<24, ocg<8) -> 2 oy x 8 oc; full occupancy
// =====================================================================
__global__ __launch_bounds__(192) void conv3_k(const float* __restrict__ cw3,
                                               const float* __restrict__ cb3) {
    __shared__ __align__(16) float s_in[16 * 4 * 26];   // 1664
    __shared__ __align__(16) float s_w[144 * 68];       // [rem][oc], stride 68
    const int oyp = blockIdx.x, n = blockIdx.y, tid = threadIdx.x;
    const int ox = tid % 24, ocg = tid / 24;
    ull acc[2][4];
#pragma unroll
    for (int i = 0; i < 2; i++)
#pragma unroll
        for (int j = 0; j < 4; j++) acc[i][j] = 0ull;

    for (int c = 0; c < 4; c++) {
        __syncthreads();
        for (int idx = tid; idx < 1664; idx += 192) {
            int icl = idx / 104, rem = idx % 104;
            int r = rem / 26, ix = rem % 26;
            s_in[idx] = g_a2[((n * 64 + c * 16 + icl) * 26 + 2 * oyp + r) * 26 + ix];
        }
        for (int idx = tid; idx < 9216; idx += 192) {
            int oc = idx / 144, rem = idx % 144;
            s_w[rem * 68 + oc] = cw3[oc * 576 + c * 144 + rem];
        }
        __syncthreads();
        for (int icl = 0; icl < 16; icl++)
#pragma unroll
            for (int ky = 0; ky < 3; ky++) {
                const float* r0 = &s_in[(icl * 4 + ky) * 26 + ox];
                const float* r1 = r0 + 26;
                float xw[3] = {r0[0], r0[1], r0[2]};
                float yw[3] = {r1[0], r1[1], r1[2]};
                const int base = (icl * 9 + ky * 3) * 68 + ocg * 8;
#pragma unroll
                for (int kx = 0; kx < 3; kx++) {
                    ull xp = pk2(xw[kx]);
                    ull yp = pk2(yw[kx]);
                    const ulonglong2* wp = (const ulonglong2*)&s_w[base + kx * 68];
                    ulonglong2 W0 = wp[0], W1 = wp[1];
                    acc[0][0] = fma2(xp, W0.x, acc[0][0]);
                    acc[0][1] = fma2(xp, W0.y, acc[0][1]);
                    acc[0][2] = fma2(xp, W1.x, acc[0][2]);
                    acc[0][3] = fma2(xp, W1.y, acc[0][3]);
                    acc[1][0] = fma2(yp, W0.x, acc[1][0]);
                    acc[1][1] = fma2(yp, W0.y, acc[1][1]);
                    acc[1][2] = fma2(yp, W1.x, acc[1][2]);
                    acc[1][3] = fma2(yp, W1.y, acc[1][3]);
                }
            }
    }
#pragma unroll
    for (int loy = 0; loy < 2; loy++) {
        int oyg = oyp * 2 + loy;
#pragma unroll
        for (int j = 0; j < 4; j++) {
            int oc = ocg * 8 + 2 * j;
            float lo, hi;
            unpk(acc[loy][j], lo, hi);
            g_a3[((n * 64 + oc) * 24 + oyg) * 24 + ox] = fmaxf(lo + cb3[oc], 0.f);
            g_a3[((n * 64 + oc + 1) * 24 + oyg) * 24 + ox] = fmaxf(hi + cb3[oc + 1], 0.f);
        }
    }
}

// =====================================================================
// fc1 split-K: Kc=256, grid (2,2,145) = 580 blocks; 64x64 tile, 4x4/thread (f32x2)
// kb 0..143: g_a3 cols; kb 144: 90 cols of history.
// =====================================================================
__global__ __launch_bounds__(256) void fc1_k(const float* __restrict__ hist,
                                             const float* __restrict__ w1) {
    __shared__ __align__(16) float Xs[32 * 68];   // [kk][b]
    __shared__ __align__(16) float Ws[32 * 68];   // [kk][j]
    const int kb = blockIdx.z, b0 = blockIdx.x * 64, j0 = blockIdx.y * 64;
    const int tid = threadIdx.x;
    const int klen = (kb == 144) ? 90 : 256;
    const int kbase = kb * 256;
    const int tb = tid & 15, tj = tid >> 4;
    ull acc[4][2];
#pragma unroll
    for (int i = 0; i < 4; i++) { acc[i][0] = 0ull; acc[i][1] = 0ull; }

    for (int ks = 0; ks < klen; ks += 32) {
        __syncthreads();
#pragma unroll
        for (int i = 0; i < 4; i++) {
            int e = tid + i * 256;
            int b = e >> 4, kh = e & 15;
            int k = ks + kh * 2;
            float2 xv = make_float2(0.f, 0.f), wv = make_float2(0.f, 0.f);
            if (k < klen) {
                xv = (kb == 144) ? *(const float2*)&hist[(b0 + b) * 90 + k]
                                 : *(const float2*)&g_a3[(b0 + b) * 36864 + kbase + k];
                wv = *(const float2*)&w1[(j0 + b) * 36954 + kbase + k];
            }
            Xs[(kh * 2) * 68 + b] = xv.x;
            Xs[(kh * 2 + 1) * 68 + b] = xv.y;
            Ws[(kh * 2) * 68 + b] = wv.x;
            Ws[(kh * 2 + 1) * 68 + b] = wv.y;
        }
        __syncthreads();
#pragma unroll
        for (int kk = 0; kk < 32; kk++) {
            ulonglong2 W = *(const ulonglong2*)&Ws[kk * 68 + tj * 4];
#pragma unroll
            for (int i = 0; i < 4; i++) {
                ull xp = pk2(Xs[kk * 68 + tb * 4 + i]);
                acc[i][0] = fma2(xp, W.x, acc[i][0]);
                acc[i][1] = fma2(xp, W.y, acc[i][1]);
            }
        }
    }
#pragma unroll
    for (int i = 0; i < 4; i++) {
        float* op = &g_part[(kb * 128 + b0 + tb * 4 + i) * 128 + j0 + tj * 4];
        float lo, hi;
        unpk(acc[i][0], lo, hi);
        op[0] = lo; op[1] = hi;
        unpk(acc[i][1], lo, hi);
        op[2] = lo; op[3] = hi;
    }
}

// =====================================================================
// lif1: reduce partials -> h1 (+b1); full stage-1 LIF trajectory (h1 const in t)
// =====================================================================
__global__ __launch_bounds__(256) void lif1_k(const float* __restrict__ b1) {
    int gid = blockIdx.x * 256 + threadIdx.x;
    int j = gid & 127;
    float h = b1[j];
#pragma unroll 1
    for (int kb = 0; kb < 145; kb++) h += g_part[kb * 16384 + gid];
    float mem = 0.f, syn = 0.f;
#pragma unroll
    for (int t = 0; t < 10; t++) {
        syn = ALPHA * syn + h;
        mem = BETA * mem + syn;
        float s = (mem > TH) ? 1.f : 0.f;
        mem -= s * TH;
        g_spk1[t * 16384 + gid] = s;
    }
}

// =====================================================================
// gemm2: h2[m][j2] = spk1[m] @ w2.T + b2, m = t*128+b (M=1280,N=256,K=128)
// =====================================================================
__global__ __launch_bounds__(256) void gemm2_k(const float* __restrict__ w2,
                                               const float* __restrict__ b2) {
    __shared__ float Xs[64][33];
    __shared__ float Ws[64][33];
    const int m0 = blockIdx.x * 64, j0 = blockIdx.y * 64, tid = threadIdx.x;
    const int mi0 = (tid & 15) * 4, ji0 = (tid >> 4) * 4;
    float acc[4][4];
#pragma unroll
    for (int i = 0; i < 4; i++)
#pragma unroll
        for (int j = 0; j < 4; j++) acc[i][j] = 0.f;

    for (int ks = 0; ks < 128; ks += 32) {
        __syncthreads();
#pragma unroll
        for (int i = 0; i < 8; i++) {
            int e = tid + i * 256, r = e >> 5, kk = e & 31;
            Xs[r][kk] = g_spk1[(m0 + r) * 128 + ks + kk];
            Ws[r][kk] = w2[(j0 + r) * 128 + ks + kk];
        }
        __syncthreads();
#pragma unroll
        for (int kk = 0; kk < 32; kk++) {
            float xv[4], wv[4];
#pragma unroll
            for (int i = 0; i < 4; i++) xv[i] = Xs[mi0 + i][kk];
#pragma unroll
            for (int j = 0; j < 4; j++) wv[j] = Ws[ji0 + j][kk];
#pragma unroll
            for (int i = 0; i < 4; i++)
#pragma unroll
                for (int j = 0; j < 4; j++) acc[i][j] += xv[i] * wv[j];
        }
    }
#pragma unroll
    for (int i = 0; i < 4; i++)
#pragma unroll
        for (int j = 0; j < 4; j++)
            g_h2[(m0 + mi0 + i) * 256 + j0 + ji0 + j] = acc[i][j] + b2[j0 + ji0 + j];
}

// =====================================================================
__global__ __launch_bounds__(256) void lif2_k() {
    int b = blockIdx.x, j = threadIdx.x;
    float mem = 0.f, syn = 0.f;
#pragma unroll
    for (int t = 0; t < 10; t++) {
        float h = g_h2[(t * 128 + b) * 256 + j];
        syn = ALPHA * syn + h;
        mem = BETA * mem + syn;
        float s = (mem > TH) ? 1.f : 0.f;
        mem -= s * TH;
        g_spk2[(t * 128 + b) * 256 + j] = s;
    }
}

// =====================================================================
__global__ __launch_bounds__(96) void out_k(const float* __restrict__ w3,
                                            const float* __restrict__ b3,
                                            float* __restrict__ out) {
    __shared__ float s_s[10 * 256];
    __shared__ float s_w[9 * 256];
    __shared__ float s_h[90];
    const int b = blockIdx.x, tid = threadIdx.x;

    for (int idx = tid; idx < 2560; idx += 96) {
        int t = idx >> 8, k = idx & 255;
        s_s[idx] = g_spk2[(t * 128 + b) * 256 + k];
    }
    for (int idx = tid; idx < 2304; idx += 96) s_w[idx] = w3[idx];
    __syncthreads();

    if (tid < 90) {
        int t = tid / 9, o = tid % 9;
        float a = b3[o];
        for (int k = 0; k < 256; k++) a += s_s[t * 256 + k] * s_w[o * 256 + k];
        s_h[tid] = a;
    }
    __syncthreads();

    if (tid < 9) {
        float syn = 0.f, mem = 0.f, pot = 0.f;
#pragma unroll
        for (int t = 0; t < 10; t++) {
            syn = ALPHA * syn + s_h[t * 9 + tid];
            mem = BETA * mem + syn;
            pot += mem;
        }
        out[b * 9 + tid] = pot / 10.0f;
    }
}

// =====================================================================
extern "C" void kernel_launch(void* const* d_in, const int* in_sizes, int n_in,
                              void* d_out, int out_size) {
    const float* state = (const float*)d_in[0];
    const float* hist  = (const float*)d_in[1];
    const float* cw1 = (const float*)d_in[2];
    const float* cb1 = (const float*)d_in[3];
    const float* cw2 = (const float*)d_in[4];
    const float* cb2 = (const float*)d_in[5];
    const float* cw3 = (const float*)d_in[6];
    const float* cb3 = (const float*)d_in[7];
    const float* w1  = (const float*)d_in[8];
    const float* b1  = (const float*)d_in[9];
    const float* w2  = (const float*)d_in[10];
    const float* b2  = (const float*)d_in[11];
    const float* w3  = (const float*)d_in[12];
    const float* b3  = (const float*)d_in[13];
    float* out = (float*)d_out;

    conv1_k<<<dim3(55, 128), 128>>>(state, cw1, cb1);
    conv2_k<<<dim3(13, 128), 224>>>(cw2, cb2);
    conv3_k<<<dim3(12, 128), 192>>>(cw3, cb3);
    fc1_k<<<dim3(2, 2, 145), 256>>>(hist, w1);
    lif1_k<<<64, 256>>>(b1);
    gemm2_k<<<dim3(20, 4), 256>>>(w2, b2);
    lif2_k<<<128, 256>>>();
    out_k<<<128, 96>>>(w3, b3, out);
}

// round 10
// speedup vs baseline: 1.4830x; 1.1895x over previous
#include <cuda_runtime.h>

#define ALPHA 0.9f
#define BETA  0.8f
#define TH    1.0f

typedef unsigned long long ull;

__device__ __forceinline__ ull fma2(ull a, ull b, ull c) {
    ull d;
    asm("fma.rn.f32x2 %0, %1, %2, %3;" : "=l"(d) : "l"(a), "l"(b), "l"(c));
    return d;
}
__device__ __forceinline__ ull pk2(float v) {
    ull r;
    asm("mov.b64 %0, {%1, %2};" : "=l"(r) : "f"(v), "f"(v));
    return r;
}
__device__ __forceinline__ void unpk(ull a, float& lo, float& hi) {
    asm("mov.b64 {%0, %1}, %2;" : "=f"(lo), "=f"(hi) : "l"(a));
}

// ---------------- scratch (device globals; no allocation) ----------------
__device__ float g_a1[128 * 32 * 55 * 55];
__device__ float g_a2[128 * 64 * 26 * 26];
__device__ float g_a3[128 * 64 * 24 * 24];
__device__ float g_part[145 * 128 * 128];
__device__ float g_spk1[10 * 128 * 128];
__device__ float g_h2[10 * 128 * 256];
__device__ float g_spk2[10 * 128 * 256];

// =====================================================================
// conv1: (128,3,224,224)->(128,32,55,55), 8x8 s4, ReLU.
// grid (14,128), 512 thr, dyn smem 79296B (2 blocks/SM, 32 warps)
// block covers 4 oy; thread (oyl, p<28: ox pair, ocg<4: 8 oc packed)
// =====================================================================
__global__ __launch_bounds__(512, 2) void conv1_k(const float* __restrict__ state,
                                                  const float* __restrict__ cw1,
                                                  const float* __restrict__ cb1) {
    extern __shared__ __align__(16) float sm[];
    float* s_in = sm;                 // [ic*20 + r][228], 13680 floats
    float* s_w  = sm + 13680;         // [rem][oc] stride 32, 6144 floats
    const int oyq = blockIdx.x, n = blockIdx.y, tid = threadIdx.x;

    for (int idx = tid; idx < 13440; idx += 512) {
        int row = idx / 224, ix = idx % 224;      // row = ic*20 + r
        int ic = row / 20, r = row % 20;
        int rg = 16 * oyq + r;
        if (rg < 224)
            s_in[row * 228 + ix] = state[((n * 3 + ic) * 224 + rg) * 224 + ix];
    }
    for (int idx = tid; idx < 6144; idx += 512) {
        int oc = idx / 192, rem = idx % 192;
        s_w[rem * 32 + oc] = cw1[idx];
    }
    __syncthreads();

    const int oyl = tid >> 7, t = tid & 127;
    const int oy = 4 * oyq + oyl;
    if (t < 112 && oy < 55) {
        const int p = t % 28, ocg = t / 28;
        ull acc[2][4];
#pragma unroll
        for (int i = 0; i < 2; i++)
#pragma unroll
            for (int j = 0; j < 4; j++) acc[i][j] = 0ull;

        for (int ic = 0; ic < 3; ic++)
#pragma unroll
            for (int ky = 0; ky < 8; ky++) {
                const float* ip = &s_in[(ic * 20 + oyl * 4 + ky) * 228 + 8 * p];
                float4 wa = *(const float4*)ip;
                float4 wb = *(const float4*)(ip + 4);
                float4 wc = *(const float4*)(ip + 8);
                float win[12] = {wa.x, wa.y, wa.z, wa.w, wb.x, wb.y, wb.z, wb.w,
                                 wc.x, wc.y, wc.z, wc.w};
                const int base = (ic * 64 + ky * 8) * 32 + ocg * 8;
#pragma unroll
                for (int kx = 0; kx < 8; kx++) {
                    ull x0 = pk2(win[kx]);
                    ull x1 = pk2(win[kx + 4]);
                    const ulonglong2* wp = (const ulonglong2*)&s_w[base + kx * 32];
                    ulonglong2 W0 = wp[0], W1 = wp[1];
                    acc[0][0] = fma2(x0, W0.x, acc[0][0]);
                    acc[0][1] = fma2(x0, W0.y, acc[0][1]);
                    acc[0][2] = fma2(x0, W1.x, acc[0][2]);
                    acc[0][3] = fma2(x0, W1.y, acc[0][3]);
                    acc[1][0] = fma2(x1, W0.x, acc[1][0]);
                    acc[1][1] = fma2(x1, W0.y, acc[1][1]);
                    acc[1][2] = fma2(x1, W1.x, acc[1][2]);
                    acc[1][3] = fma2(x1, W1.y, acc[1][3]);
                }
            }
        const int ox0 = 2 * p, ox1 = 2 * p + 1;
#pragma unroll
        for (int j = 0; j < 4; j++) {
            int oc = ocg * 8 + 2 * j;
            float b0v = cb1[oc], b1v = cb1[oc + 1];
            float l0, h0, l1, h1;
            unpk(acc[0][j], l0, h0);
            unpk(acc[1][j], l1, h1);
            float* op0 = &g_a1[((n * 32 + oc) * 55 + oy) * 55];
            float* op1 = op0 + 55 * 55;
            op0[ox0] = fmaxf(l0 + b0v, 0.f);
            op1[ox0] = fmaxf(h0 + b1v, 0.f);
            if (ox1 < 55) {
                op0[ox1] = fmaxf(l1 + b0v, 0.f);
                op1[ox1] = fmaxf(h1 + b1v, 0.f);
            }
        }
    }
}

// =====================================================================
// conv2: (128,32,55,55)->(128,64,26,26), 4x4 s2, ReLU.
// grid (7,128), 208 thr, dyn smem 52736B (4 blocks/SM, 28 warps)
// block covers 4 oy; thread tile 2oy x 2ox x 8oc (16 f32x2 accs)
// =====================================================================
__global__ __launch_bounds__(208, 4) void conv2_k(const float* __restrict__ cw2,
                                                  const float* __restrict__ cb2) {
    extern __shared__ __align__(16) float sm[];
    float* s_in = sm;                 // [icl*10 + r][56], 4480 floats
    float* s_w  = sm + 4480;          // [rem][oc] stride 68, 8704 floats
    const int oyq = blockIdx.x, n = blockIdx.y, tid = threadIdx.x;
    const int oypl = tid / 104, t = tid % 104;
    const int oxp = t % 13, ocg = t / 13;
    const int oy0 = 4 * oyq + 2 * oypl;
    ull acc[2][2][4];
#pragma unroll
    for (int a = 0; a < 2; a++)
#pragma unroll
        for (int b = 0; b < 2; b++)
#pragma unroll
            for (int j = 0; j < 4; j++) acc[a][b][j] = 0ull;

    for (int c = 0; c < 4; c++) {
        __syncthreads();
        for (int idx = tid; idx < 4400; idx += 208) {
            int icl = idx / 550, rem = idx % 550;
            int r = rem / 55, ix = rem % 55;
            int rg = 8 * oyq + r;
            s_in[(icl * 10 + r) * 56 + ix] =
                (rg < 55) ? g_a1[((n * 32 + c * 8 + icl) * 55 + rg) * 55 + ix] : 0.f;
        }
        for (int idx = tid; idx < 8192; idx += 208) {
            int oc = idx >> 7, rem = idx & 127;
            s_w[rem * 68 + oc] = cw2[oc * 512 + c * 128 + rem];
        }
        __syncthreads();
        for (int icl = 0; icl < 8; icl++)
#pragma unroll
            for (int ky = 0; ky < 4; ky++) {
                const float* r0 = &s_in[(icl * 10 + 4 * oypl + ky) * 56 + 4 * oxp];
                const float* r1 = r0 + 2 * 56;
                float2 a0 = *(const float2*)r0;
                float2 a1 = *(const float2*)(r0 + 2);
                float2 a2 = *(const float2*)(r0 + 4);
                float2 c0 = *(const float2*)r1;
                float2 c1 = *(const float2*)(r1 + 2);
                float2 c2 = *(const float2*)(r1 + 4);
                float xv[6] = {a0.x, a0.y, a1.x, a1.y, a2.x, a2.y};
                float yv[6] = {c0.x, c0.y, c1.x, c1.y, c2.x, c2.y};
                const int base = (icl * 16 + ky * 4) * 68 + ocg * 8;
#pragma unroll
                for (int kx = 0; kx < 4; kx++) {
                    const ulonglong2* wp = (const ulonglong2*)&s_w[base + kx * 68];
                    ulonglong2 W0 = wp[0], W1 = wp[1];
                    ull x0 = pk2(xv[kx]), x1 = pk2(xv[kx + 2]);
                    ull y0 = pk2(yv[kx]), y1 = pk2(yv[kx + 2]);
                    acc[0][0][0] = fma2(x0, W0.x, acc[0][0][0]);
                    acc[0][0][1] = fma2(x0, W0.y, acc[0][0][1]);
                    acc[0][0][2] = fma2(x0, W1.x, acc[0][0][2]);
                    acc[0][0][3] = fma2(x0, W1.y, acc[0][0][3]);
                    acc[0][1][0] = fma2(x1, W0.x, acc[0][1][0]);
                    acc[0][1][1] = fma2(x1, W0.y, acc[0][1][1]);
                    acc[0][1][2] = fma2(x1, W1.x, acc[0][1][2]);
                    acc[0][1][3] = fma2(x1, W1.y, acc[0][1][3]);
                    acc[1][0][0] = fma2(y0, W0.x, acc[1][0][0]);
                    acc[1][0][1] = fma2(y0, W0.y, acc[1][0][1]);
                    acc[1][0][2] = fma2(y0, W1.x, acc[1][0][2]);
                    acc[1][0][3] = fma2(y0, W1.y, acc[1][0][3]);
                    acc[1][1][0] = fma2(y1, W0.x, acc[1][1][0]);
                    acc[1][1][1] = fma2(y1, W0.y, acc[1][1][1]);
                    acc[1][1][2] = fma2(y1, W1.x, acc[1][1][2]);
                    acc[1][1][3] = fma2(y1, W1.y, acc[1][1][3]);
                }
            }
    }
#pragma unroll
    for (int loy = 0; loy < 2; loy++) {
        int oy = oy0 + loy;
        if (oy < 26) {
#pragma unroll
            for (int lox = 0; lox < 2; lox++) {
                int ox = 2 * oxp + lox;
#pragma unroll
                for (int j = 0; j < 4; j++) {
                    int oc = ocg * 8 + 2 * j;
                    float lo, hi;
                    unpk(acc[loy][lox][j], lo, hi);
                    g_a2[((n * 64 + oc) * 26 + oy) * 26 + ox] = fmaxf(lo + cb2[oc], 0.f);
                    g_a2[((n * 64 + oc + 1) * 26 + oy) * 26 + ox] = fmaxf(hi + cb2[oc + 1], 0.f);
                }
            }
        }
    }
}

// =====================================================================
// conv3: (128,64,26,26)->(128,64,24,24), 3x3 s1, ReLU.
// grid (6,128), 192 thr, dyn smem 49920B (4 blocks/SM, 24 warps)
// block covers 4 oy; thread tile 2oy x 2ox x 8oc
// =====================================================================
__global__ __launch_bounds__(192, 4) void conv3_k(const float* __restrict__ cw3,
                                                  const float* __restrict__ cb3) {
    extern __shared__ __align__(16) float sm[];
    float* s_in = sm;                 // [icl*6 + r][28], 2688 floats
    float* s_w  = sm + 2688;          // [rem][oc] stride 68, 9792 floats
    const int oyq = blockIdx.x, n = blockIdx.y, tid = threadIdx.x;
    const int oypl = tid / 96, t = tid % 96;
    const int oxp = t % 12, ocg = t / 12;
    ull acc[2][2][4];
#pragma unroll
    for (int a = 0; a < 2; a++)
#pragma unroll
        for (int b = 0; b < 2; b++)
#pragma unroll
            for (int j = 0; j < 4; j++) acc[a][b][j] = 0ull;

    for (int c = 0; c < 4; c++) {
        __syncthreads();
        for (int idx = tid; idx < 2496; idx += 192) {
            int icl = idx / 156, rem = idx % 156;
            int r = rem / 26, ix = rem % 26;
            s_in[(icl * 6 + r) * 28 + ix] =
                g_a2[((n * 64 + c * 16 + icl) * 26 + 4 * oyq + r) * 26 + ix];
        }
        for (int idx = tid; idx < 9216; idx += 192) {
            int oc = idx / 144, rem = idx % 144;
            s_w[rem * 68 + oc] = cw3[oc * 576 + c * 144 + rem];
        }
        __syncthreads();
        for (int icl = 0; icl < 16; icl++)
#pragma unroll
            for (int ky = 0; ky < 3; ky++) {
                const float* r0 = &s_in[(icl * 6 + 2 * oypl + ky) * 28 + 2 * oxp];
                const float* r1 = r0 + 28;
                float2 a0 = *(const float2*)r0;
                float2 a1 = *(const float2*)(r0 + 2);
                float2 c0 = *(const float2*)r1;
                float2 c1 = *(const float2*)(r1 + 2);
                float xv[4] = {a0.x, a0.y, a1.x, a1.y};
                float yv[4] = {c0.x, c0.y, c1.x, c1.y};
                const int base = (icl * 9 + ky * 3) * 68 + ocg * 8;
#pragma unroll
                for (int kx = 0; kx < 3; kx++) {
                    const ulonglong2* wp = (const ulonglong2*)&s_w[base + kx * 68];
                    ulonglong2 W0 = wp[0], W1 = wp[1];
                    ull x0 = pk2(xv[kx]), x1 = pk2(xv[kx + 1]);
                    ull y0 = pk2(yv[kx]), y1 = pk2(yv[kx + 1]);
                    acc[0][0][0] = fma2(x0, W0.x, acc[0][0][0]);
                    acc[0][0][1] = fma2(x0, W0.y, acc[0][0][1]);
                    acc[0][0][2] = fma2(x0, W1.x, acc[0][0][2]);
                    acc[0][0][3] = fma2(x0, W1.y, acc[0][0][3]);
                    acc[0][1][0] = fma2(x1, W0.x, acc[0][1][0]);
                    acc[0][1][1] = fma2(x1, W0.y, acc[0][1][1]);
                    acc[0][1][2] = fma2(x1, W1.x, acc[0][1][2]);
                    acc[0][1][3] = fma2(x1, W1.y, acc[0][1][3]);
                    acc[1][0][0] = fma2(y0, W0.x, acc[1][0][0]);
                    acc[1][0][1] = fma2(y0, W0.y, acc[1][0][1]);
                    acc[1][0][2] = fma2(y0, W1.x, acc[1][0][2]);
                    acc[1][0][3] = fma2(y0, W1.y, acc[1][0][3]);
                    acc[1][1][0] = fma2(y1, W0.x, acc[1][1][0]);
                    acc[1][1][1] = fma2(y1, W0.y, acc[1][1][1]);
                    acc[1][1][2] = fma2(y1, W1.x, acc[1][1][2]);
                    acc[1][1][3] = fma2(y1, W1.y, acc[1][1][3]);
                }
            }
    }
#pragma unroll
    for (int loy = 0; loy < 2; loy++) {
        int oy = 4 * oyq + 2 * oypl + loy;
#pragma unroll
        for (int lox = 0; lox < 2; lox++) {
            int ox = 2 * oxp + lox;
#pragma unroll
            for (int j = 0; j < 4; j++) {
                int oc = ocg * 8 + 2 * j;
                float lo, hi;
                unpk(acc[loy][lox][j], lo, hi);
                g_a3[((n * 64 + oc) * 24 + oy) * 24 + ox] = fmaxf(lo + cb3[oc], 0.f);
                g_a3[((n * 64 + oc + 1) * 24 + oy) * 24 + ox] = fmaxf(hi + cb3[oc + 1], 0.f);
            }
        }
    }
}

// =====================================================================
// fc1 split-K: Kc=256, grid (2,2,145); 64x64 tile, 4x4/thread (f32x2)
// =====================================================================
__global__ __launch_bounds__(256) void fc1_k(const float* __restrict__ hist,
                                             const float* __restrict__ w1) {
    __shared__ __align__(16) float Xs[32 * 68];
    __shared__ __align__(16) float Ws[32 * 68];
    const int kb = blockIdx.z, b0 = blockIdx.x * 64, j0 = blockIdx.y * 64;
    const int tid = threadIdx.x;
    const int klen = (kb == 144) ? 90 : 256;
    const int kbase = kb * 256;
    const int tb = tid & 15, tj = tid >> 4;
    ull acc[4][2];
#pragma unroll
    for (int i = 0; i < 4; i++) { acc[i][0] = 0ull; acc[i][1] = 0ull; }

    for (int ks = 0; ks < klen; ks += 32) {
        __syncthreads();
#pragma unroll
        for (int i = 0; i < 4; i++) {
            int e = tid + i * 256;
            int b = e >> 4, kh = e & 15;
            int k = ks + kh * 2;
            float2 xv = make_float2(0.f, 0.f), wv = make_float2(0.f, 0.f);
            if (k < klen) {
                xv = (kb == 144) ? *(const float2*)&hist[(b0 + b) * 90 + k]
                                 : *(const float2*)&g_a3[(b0 + b) * 36864 + kbase + k];
                wv = *(const float2*)&w1[(j0 + b) * 36954 + kbase + k];
            }
            Xs[(kh * 2) * 68 + b] = xv.x;
            Xs[(kh * 2 + 1) * 68 + b] = xv.y;
            Ws[(kh * 2) * 68 + b] = wv.x;
            Ws[(kh * 2 + 1) * 68 + b] = wv.y;
        }
        __syncthreads();
#pragma unroll
        for (int kk = 0; kk < 32; kk++) {
            ulonglong2 W = *(const ulonglong2*)&Ws[kk * 68 + tj * 4];
#pragma unroll
            for (int i = 0; i < 4; i++) {
                ull xp = pk2(Xs[kk * 68 + tb * 4 + i]);
                acc[i][0] = fma2(xp, W.x, acc[i][0]);
                acc[i][1] = fma2(xp, W.y, acc[i][1]);
            }
        }
    }
#pragma unroll
    for (int i = 0; i < 4; i++) {
        float* op = &g_part[(kb * 128 + b0 + tb * 4 + i) * 128 + j0 + tj * 4];
        float lo, hi;
        unpk(acc[i][0], lo, hi);
        op[0] = lo; op[1] = hi;
        unpk(acc[i][1], lo, hi);
        op[2] = lo; op[3] = hi;
    }
}

// =====================================================================
__global__ __launch_bounds__(256) void lif1_k(const float* __restrict__ b1) {
    int gid = blockIdx.x * 256 + threadIdx.x;
    int j = gid & 127;
    float h = b1[j];
#pragma unroll 1
    for (int kb = 0; kb < 145; kb++) h += g_part[kb * 16384 + gid];
    float mem = 0.f, syn = 0.f;
#pragma unroll
    for (int t = 0; t < 10; t++) {
        syn = ALPHA * syn + h;
        mem = BETA * mem + syn;
        float s = (mem > TH) ? 1.f : 0.f;
        mem -= s * TH;
        g_spk1[t * 16384 + gid] = s;
    }
}

// =====================================================================
__global__ __launch_bounds__(256) void gemm2_k(const float* __restrict__ w2,
                                               const float* __restrict__ b2) {
    __shared__ float Xs[64][33];
    __shared__ float Ws[64][33];
    const int m0 = blockIdx.x * 64, j0 = blockIdx.y * 64, tid = threadIdx.x;
    const int mi0 = (tid & 15) * 4, ji0 = (tid >> 4) * 4;
    float acc[4][4];
#pragma unroll
    for (int i = 0; i < 4; i++)
#pragma unroll
        for (int j = 0; j < 4; j++) acc[i][j] = 0.f;

    for (int ks = 0; ks < 128; ks += 32) {
        __syncthreads();
#pragma unroll
        for (int i = 0; i < 8; i++) {
            int e = tid + i * 256, r = e >> 5, kk = e & 31;
            Xs[r][kk] = g_spk1[(m0 + r) * 128 + ks + kk];
            Ws[r][kk] = w2[(j0 + r) * 128 + ks + kk];
        }
        __syncthreads();
#pragma unroll
        for (int kk = 0; kk < 32; kk++) {
            float xv[4], wv[4];
#pragma unroll
            for (int i = 0; i < 4; i++) xv[i] = Xs[mi0 + i][kk];
#pragma unroll
            for (int j = 0; j < 4; j++) wv[j] = Ws[ji0 + j][kk];
#pragma unroll
            for (int i = 0; i < 4; i++)
#pragma unroll
                for (int j = 0; j < 4; j++) acc[i][j] += xv[i] * wv[j];
        }
    }
#pragma unroll
    for (int i = 0; i < 4; i++)
#pragma unroll
        for (int j = 0; j < 4; j++)
            g_h2[(m0 + mi0 + i) * 256 + j0 + ji0 + j] = acc[i][j] + b2[j0 + ji0 + j];
}

// =====================================================================
__global__ __launch_bounds__(256) void lif2_k() {
    int b = blockIdx.x, j = threadIdx.x;
    float mem = 0.f, syn = 0.f;
#pragma unroll
    for (int t = 0; t < 10; t++) {
        float h = g_h2[(t * 128 + b) * 256 + j];
        syn = ALPHA * syn + h;
        mem = BETA * mem + syn;
        float s = (mem > TH) ? 1.f : 0.f;
        mem -= s * TH;
        g_spk2[(t * 128 + b) * 256 + j] = s;
    }
}

// =====================================================================
__global__ __launch_bounds__(96) void out_k(const float* __restrict__ w3,
                                            const float* __restrict__ b3,
                                            float* __restrict__ out) {
    __shared__ float s_s[10 * 256];
    __shared__ float s_w[9 * 256];
    __shared__ float s_h[90];
    const int b = blockIdx.x, tid = threadIdx.x;

    for (int idx = tid; idx < 2560; idx += 96) {
        int t = idx >> 8, k = idx & 255;
        s_s[idx] = g_spk2[(t * 128 + b) * 256 + k];
    }
    for (int idx = tid; idx < 2304; idx += 96) s_w[idx] = w3[idx];
    __syncthreads();

    if (tid < 90) {
        int t = tid / 9, o = tid % 9;
        float a = b3[o];
        for (int k = 0; k < 256; k++) a += s_s[t * 256 + k] * s_w[o * 256 + k];
        s_h[tid] = a;
    }
    __syncthreads();

    if (tid < 9) {
        float syn = 0.f, mem = 0.f, pot = 0.f;
#pragma unroll
        for (int t = 0; t < 10; t++) {
            syn = ALPHA * syn + s_h[t * 9 + tid];
            mem = BETA * mem + syn;
            pot += mem;
        }
        out[b * 9 + tid] = pot / 10.0f;
    }
}

// =====================================================================
extern "C" void kernel_launch(void* const* d_in, const int* in_sizes, int n_in,
                              void* d_out, int out_size) {
    const float* state = (const float*)d_in[0];
    const float* hist  = (const float*)d_in[1];
    const float* cw1 = (const float*)d_in[2];
    const float* cb1 = (const float*)d_in[3];
    const float* cw2 = (const float*)d_in[4];
    const float* cb2 = (const float*)d_in[5];
    const float* cw3 = (const float*)d_in[6];
    const float* cb3 = (const float*)d_in[7];
    const float* w1  = (const float*)d_in[8];
    const float* b1  = (const float*)d_in[9];
    const float* w2  = (const float*)d_in[10];
    const float* b2  = (const float*)d_in[11];
    const float* w3  = (const float*)d_in[12];
    const float* b3  = (const float*)d_in[13];
    float* out = (float*)d_out;

    const int smem1 = 79296, smem2 = 52736, smem3 = 49920;
    cudaFuncSetAttribute(conv1_k, cudaFuncAttributeMaxDynamicSharedMemorySize, smem1);
    cudaFuncSetAttribute(conv2_k, cudaFuncAttributeMaxDynamicSharedMemorySize, smem2);
    cudaFuncSetAttribute(conv3_k, cudaFuncAttributeMaxDynamicSharedMemorySize, smem3);

    conv1_k<<<dim3(14, 128), 512, smem1>>>(state, cw1, cb1);
    conv2_k<<<dim3(7, 128), 208, smem2>>>(cw2, cb2);
    conv3_k<<<dim3(6, 128), 192, smem3>>>(cw3, cb3);
    fc1_k<<<dim3(2, 2, 145), 256>>>(hist, w1);
    lif1_k<<<64, 256>>>(b1);
    gemm2_k<<<dim3(20, 4), 256>>>(w2, b2);
    lif2_k<<<128, 256>>>();
    out_k<<<128, 96>>>(w3, b3, out);
}